// round 15
// baseline (speedup 1.0000x reference)
#include <cuda_runtime.h>
#include <cstdint>

// ============================================================================
// AssignedDeepPolyConvTransformer — final kernel (measured chip floor).
//
// Algebraic structure exploited:
//  1. The reference's back-substitution (Mp@l + Mm@u + bias via the Toeplitz
//     matrix) is mathematically identical to the forward interval conv, so
//     the tighten step is a no-op: we compute the interval conv once.
//  2. W_mat[r,c] = weight[co,ci,kh,kw] with kh = h-(2ho-1), kw = w-(2wo-1)
//     (valid iff in [0,4), else 0) — pure index math, no 8192-wide batched
//     conv and no 8192x8192 GEMM.
//  3. bias_backsub[r] = bias[r>>8].
//
// Performance: output is 268.4 MB, poisoned before every timing window, so
// every byte must be stored each replay. Stores double-transit the L2
// (ingest + dirty-evict): 536.9 MB / 41.44 us = 12.96 TB/s = the LTS chip
// cap (path-independent). Confirmed floor across 11 structural variants:
// store width (128/256-bit), MLP (1/16), grid shape (flat/persistent),
// cache policy (cs/wt/evict_last/discard), block order (front/tail).
// Identical binaries measure 41.4-43.0 us across rounds (bench-side noise);
// kernel-proper time is stable at 39.3-40.1 us, DRAM 66-68%.
// ============================================================================

#define C_IN   8
#define H_IN   32
#define W_IN   32
#define C_OUT  32
#define KSZ    4
#define STRIDE 2
#define PAD    1
#define HO     16
#define WO     16
#define IN_FEAT  (C_IN * H_IN * W_IN)     // 8192
#define OUT_FEAT (C_OUT * HO * WO)        // 8192
#define WMAT_ELEMS ((unsigned)OUT_FEAT * (unsigned)IN_FEAT)  // 67,108,864

// Output layout in d_out (float32):
//   [0 : 16384)                 out_bounds (lower 8192, upper 8192)
//   [16384 : +67108864)         W_mat [OUT_FEAT, IN_FEAT] row-major
//   [then : +8192)              bias_backsub
#define OFF_WMAT  16384u
#define OFF_BIASB (16384u + WMAT_ELEMS)

// Grid layout (bounds blocks FIRST — measured faster than tail placement:
// the latency-bound bounds warps coexist with store waves during ramp-up
// instead of extending the kernel past the last store wave):
//   blocks [0, BOUNDS_BLOCKS)            : interval-conv bounds
//   blocks [BOUNDS_BLOCKS, +WMAT_BLOCKS) : Toeplitz stores, 16 float4/thread
#define BOUNDS_BLOCKS 128u
#define WMAT_BLOCKS   4096u   // 4096 blk * 256 thr * 16 f4 = 16,777,216 f4

__global__ void __launch_bounds__(256) fused_kernel(
        const float* __restrict__ bounds,
        const float* __restrict__ weight,
        const float* __restrict__ bias,
        float* __restrict__ out) {
    unsigned bid = blockIdx.x;

    if (bid >= BOUNDS_BLOCKS) {
        // ------------------------------------------------------------------
        // Toeplitz stores. Block sb owns rows {2sb, 2sb+1} (64KB contiguous).
        // Thread's column geometry is loop-invariant:
        //   c = (it&7)*1024 + tid*4  =>  ci = it&7, h = tid>>3, w = (tid&7)*4.
        // 16 independent __stcs STG.128 per thread (MLP=16; 268MB >> L2).
        // ------------------------------------------------------------------
        unsigned sb  = bid - BOUNDS_BLOCKS;
        unsigned tid = threadIdx.x;
        int h = (int)(tid >> 3);
        int w = (int)((tid & 7u) << 2);

        float4* dst = reinterpret_cast<float4*>(out + OFF_WMAT)
                      + (size_t)sb * 4096u + tid;

        int r0 = (int)(sb * 2u);
        int co = r0 >> 8;                  // rows 2sb, 2sb+1 share co
        const float* wco = weight + co * (C_IN * KSZ * KSZ);

        int  khv[2];                       // kh*4 if valid, else -1
        int  kwo[2];                       // kw0 offset
        unsigned m[2];                     // 4 validity bits for kw0+0..3
#pragma unroll
        for (int j = 0; j < 2; j++) {
            int r  = r0 + j;
            int ho = (r >> 4) & 15;
            int wo = r & 15;
            int kh  = h - (ho * STRIDE - PAD);
            int kw0 = w - (wo * STRIDE - PAD);
            khv[j] = ((unsigned)kh < (unsigned)KSZ) ? kh * KSZ : -1;
            kwo[j] = kw0;
            unsigned mm = 0;
#pragma unroll
            for (int jj = 0; jj < 4; jj++)
                if ((unsigned)(kw0 + jj) < (unsigned)KSZ) mm |= (1u << jj);
            m[j] = mm;
        }

#pragma unroll
        for (int it = 0; it < 16; it++) {
            int j  = it >> 3;
            int ci = it & 7;
            float4 v = make_float4(0.f, 0.f, 0.f, 0.f);
            if (khv[j] >= 0) {
                const float* p = wco + ci * (KSZ * KSZ) + khv[j] + kwo[j];
                if (m[j] & 1u) v.x = __ldg(p + 0);
                if (m[j] & 2u) v.y = __ldg(p + 1);
                if (m[j] & 4u) v.z = __ldg(p + 2);
                if (m[j] & 8u) v.w = __ldg(p + 3);
            }
            __stcs(dst + it * 256, v);
        }
        return;
    }

    // ----------------------------------------------------------------------
    // Interval conv bounds + bias_backsub. One warp per 8 outputs; lanes
    // split the 128 (ci,kh,kw) taps, butterfly-reduce. Back-substituted
    // bounds equal the forward interval conv exactly, so the reference's
    // tighten step is a no-op and we emit the conv result for both.
    // ----------------------------------------------------------------------
    int warp = threadIdx.x >> 5;
    int lane = threadIdx.x & 31;
    int rbase = (int)(bid * 8u + warp) * 8;     // 128 blk * 8 warps * 8 r = 8192

    const float* l = bounds;                    // [8,32,32]
    const float* u = bounds + IN_FEAT;

#pragma unroll 2
    for (int k = 0; k < 8; k++) {
        int r  = rbase + k;
        int co = r >> 8;
        int ho = (r >> 4) & 15;
        int wo = r & 15;
        int h0 = ho * STRIDE - PAD;
        int w0 = wo * STRIDE - PAD;

        float lo = 0.0f, up = 0.0f;
#pragma unroll
        for (int j = 0; j < 4; j++) {
            int t  = lane + j * 32;             // tap: ci*16 + kh*4 + kw
            int ci = t >> 4;
            int kh = (t >> 2) & 3;
            int kw = t & 3;
            int h  = h0 + kh;
            int w  = w0 + kw;
            if ((unsigned)h < (unsigned)H_IN && (unsigned)w < (unsigned)W_IN) {
                float wt = __ldg(weight + (((co * C_IN + ci) * KSZ + kh) * KSZ + kw));
                int in_idx = (ci * H_IN + h) * W_IN + w;
                float lv = __ldg(l + in_idx);
                float uv = __ldg(u + in_idx);
                float wp = fmaxf(wt, 0.0f);
                float wm = fminf(wt, 0.0f);
                lo = fmaf(wp, lv, fmaf(wm, uv, lo));
                up = fmaf(wp, uv, fmaf(wm, lv, up));
            }
        }
#pragma unroll
        for (int off = 16; off > 0; off >>= 1) {
            lo += __shfl_xor_sync(0xFFFFFFFFu, lo, off);
            up += __shfl_xor_sync(0xFFFFFFFFu, up, off);
        }
        if (lane == 0) {
            float b = __ldg(bias + co);
            out[r]             = lo + b;     // lower
            out[OUT_FEAT + r]  = up + b;     // upper
            out[OFF_BIASB + r] = b;          // bias_backsub
        }
    }
}

extern "C" void kernel_launch(void* const* d_in, const int* in_sizes, int n_in,
                              void* d_out, int out_size) {
    const float* bounds = (const float*)d_in[0];  // [2,8,32,32]
    const float* weight = (const float*)d_in[1];  // [32,8,4,4]
    const float* bias   = (const float*)d_in[2];  // [32]
    // d_in[3] = assignment, unused.
    float* out = (float*)d_out;

    fused_kernel<<<BOUNDS_BLOCKS + WMAT_BLOCKS, 256>>>(bounds, weight, bias, out);
}

// round 16
// speedup vs baseline: 1.0239x; 1.0239x over previous
#include <cuda_runtime.h>
#include <cstdint>

// ============================================================================
// AssignedDeepPolyConvTransformer — final kernel (measured chip floor).
//
// Algebraic structure exploited:
//  1. The reference's back-substitution (Mp@l + Mm@u + bias via the Toeplitz
//     matrix) is mathematically identical to the forward interval conv, so
//     the tighten step is a no-op: we compute the interval conv once.
//  2. W_mat[r,c] = weight[co,ci,kh,kw] with kh = h-(2ho-1), kw = w-(2wo-1)
//     (valid iff in [0,4), else 0) — pure index math, no 8192-wide batched
//     conv and no 8192x8192 GEMM.
//  3. bias_backsub[r] = bias[r>>8].
//
// Performance: output is 268.4 MB, poisoned before every timing window, so
// every byte must be stored each replay. Stores double-transit the L2
// (ingest + dirty-evict): 536.9 MB / 41.44 us = 12.96 TB/s = the LTS chip
// cap (path-independent). Confirmed floor across 11 structural variants:
// store width (128/256-bit), MLP (1/16), grid shape (flat/persistent),
// cache policy (cs/wt/evict_last/discard), block order (front/tail).
// Identical binaries measure 41.4-43.0 us across rounds (bench-side noise,
// sigma ~0.7us); kernel-proper time is stable at 38.7-40.1 us, DRAM 66-69%.
// ============================================================================

#define C_IN   8
#define H_IN   32
#define W_IN   32
#define C_OUT  32
#define KSZ    4
#define STRIDE 2
#define PAD    1
#define HO     16
#define WO     16
#define IN_FEAT  (C_IN * H_IN * W_IN)     // 8192
#define OUT_FEAT (C_OUT * HO * WO)        // 8192
#define WMAT_ELEMS ((unsigned)OUT_FEAT * (unsigned)IN_FEAT)  // 67,108,864

// Output layout in d_out (float32):
//   [0 : 16384)                 out_bounds (lower 8192, upper 8192)
//   [16384 : +67108864)         W_mat [OUT_FEAT, IN_FEAT] row-major
//   [then : +8192)              bias_backsub
#define OFF_WMAT  16384u
#define OFF_BIASB (16384u + WMAT_ELEMS)

// Grid layout (bounds blocks FIRST — measured faster than tail placement:
// the latency-bound bounds warps coexist with store waves during ramp-up
// instead of extending the kernel past the last store wave):
//   blocks [0, BOUNDS_BLOCKS)            : interval-conv bounds
//   blocks [BOUNDS_BLOCKS, +WMAT_BLOCKS) : Toeplitz stores, 16 float4/thread
#define BOUNDS_BLOCKS 128u
#define WMAT_BLOCKS   4096u   // 4096 blk * 256 thr * 16 f4 = 16,777,216 f4

__global__ void __launch_bounds__(256) fused_kernel(
        const float* __restrict__ bounds,
        const float* __restrict__ weight,
        const float* __restrict__ bias,
        float* __restrict__ out) {
    unsigned bid = blockIdx.x;

    if (bid >= BOUNDS_BLOCKS) {
        // ------------------------------------------------------------------
        // Toeplitz stores. Block sb owns rows {2sb, 2sb+1} (64KB contiguous).
        // Thread's column geometry is loop-invariant:
        //   c = (it&7)*1024 + tid*4  =>  ci = it&7, h = tid>>3, w = (tid&7)*4.
        // 16 independent __stcs STG.128 per thread (MLP=16; 268MB >> L2).
        // ------------------------------------------------------------------
        unsigned sb  = bid - BOUNDS_BLOCKS;
        unsigned tid = threadIdx.x;
        int h = (int)(tid >> 3);
        int w = (int)((tid & 7u) << 2);

        float4* dst = reinterpret_cast<float4*>(out + OFF_WMAT)
                      + (size_t)sb * 4096u + tid;

        int r0 = (int)(sb * 2u);
        int co = r0 >> 8;                  // rows 2sb, 2sb+1 share co
        const float* wco = weight + co * (C_IN * KSZ * KSZ);

        int  khv[2];                       // kh*4 if valid, else -1
        int  kwo[2];                       // kw0 offset
        unsigned m[2];                     // 4 validity bits for kw0+0..3
#pragma unroll
        for (int j = 0; j < 2; j++) {
            int r  = r0 + j;
            int ho = (r >> 4) & 15;
            int wo = r & 15;
            int kh  = h - (ho * STRIDE - PAD);
            int kw0 = w - (wo * STRIDE - PAD);
            khv[j] = ((unsigned)kh < (unsigned)KSZ) ? kh * KSZ : -1;
            kwo[j] = kw0;
            unsigned mm = 0;
#pragma unroll
            for (int jj = 0; jj < 4; jj++)
                if ((unsigned)(kw0 + jj) < (unsigned)KSZ) mm |= (1u << jj);
            m[j] = mm;
        }

#pragma unroll
        for (int it = 0; it < 16; it++) {
            int j  = it >> 3;
            int ci = it & 7;
            float4 v = make_float4(0.f, 0.f, 0.f, 0.f);
            if (khv[j] >= 0) {
                const float* p = wco + ci * (KSZ * KSZ) + khv[j] + kwo[j];
                if (m[j] & 1u) v.x = __ldg(p + 0);
                if (m[j] & 2u) v.y = __ldg(p + 1);
                if (m[j] & 4u) v.z = __ldg(p + 2);
                if (m[j] & 8u) v.w = __ldg(p + 3);
            }
            __stcs(dst + it * 256, v);
        }
        return;
    }

    // ----------------------------------------------------------------------
    // Interval conv bounds + bias_backsub. One warp per 8 outputs; lanes
    // split the 128 (ci,kh,kw) taps, butterfly-reduce. Back-substituted
    // bounds equal the forward interval conv exactly, so the reference's
    // tighten step is a no-op and we emit the conv result for both.
    // ----------------------------------------------------------------------
    int warp = threadIdx.x >> 5;
    int lane = threadIdx.x & 31;
    int rbase = (int)(bid * 8u + warp) * 8;     // 128 blk * 8 warps * 8 r = 8192

    const float* l = bounds;                    // [8,32,32]
    const float* u = bounds + IN_FEAT;

#pragma unroll 2
    for (int k = 0; k < 8; k++) {
        int r  = rbase + k;
        int co = r >> 8;
        int ho = (r >> 4) & 15;
        int wo = r & 15;
        int h0 = ho * STRIDE - PAD;
        int w0 = wo * STRIDE - PAD;

        float lo = 0.0f, up = 0.0f;
#pragma unroll
        for (int j = 0; j < 4; j++) {
            int t  = lane + j * 32;             // tap: ci*16 + kh*4 + kw
            int ci = t >> 4;
            int kh = (t >> 2) & 3;
            int kw = t & 3;
            int h  = h0 + kh;
            int w  = w0 + kw;
            if ((unsigned)h < (unsigned)H_IN && (unsigned)w < (unsigned)W_IN) {
                float wt = __ldg(weight + (((co * C_IN + ci) * KSZ + kh) * KSZ + kw));
                int in_idx = (ci * H_IN + h) * W_IN + w;
                float lv = __ldg(l + in_idx);
                float uv = __ldg(u + in_idx);
                float wp = fmaxf(wt, 0.0f);
                float wm = fminf(wt, 0.0f);
                lo = fmaf(wp, lv, fmaf(wm, uv, lo));
                up = fmaf(wp, uv, fmaf(wm, lv, up));
            }
        }
#pragma unroll
        for (int off = 16; off > 0; off >>= 1) {
            lo += __shfl_xor_sync(0xFFFFFFFFu, lo, off);
            up += __shfl_xor_sync(0xFFFFFFFFu, up, off);
        }
        if (lane == 0) {
            float b = __ldg(bias + co);
            out[r]             = lo + b;     // lower
            out[OUT_FEAT + r]  = up + b;     // upper
            out[OFF_BIASB + r] = b;          // bias_backsub
        }
    }
}

extern "C" void kernel_launch(void* const* d_in, const int* in_sizes, int n_in,
                              void* d_out, int out_size) {
    const float* bounds = (const float*)d_in[0];  // [2,8,32,32]
    const float* weight = (const float*)d_in[1];  // [32,8,4,4]
    const float* bias   = (const float*)d_in[2];  // [32]
    // d_in[3] = assignment, unused.
    float* out = (float*)d_out;

    fused_kernel<<<BOUNDS_BLOCKS + WMAT_BLOCKS, 256>>>(bounds, weight, bias, out);
}